// round 1
// baseline (speedup 1.0000x reference)
#include <cuda_runtime.h>
#include <cuda_bf16.h>
#include <cstdint>

// ----------------------------------------------------------------------------
// PyramidResidualMoE: out = x + baseSwiGLU(x) + expert_{argmax}(x)
// Router collapses exactly to top-1 with weight p/max(p,1e-6) (== 1.0 in practice).
// Strategy: fp32 router (exact argmax) -> token compaction per expert ->
//           bf16 mma.sync GEMMs (gate|up fused N, act kernel, down with
//           residual / scatter-add epilogues).
// ----------------------------------------------------------------------------

namespace cfg {
constexpr int TOK = 8 * 2048;   // 16384 tokens
constexpr int CD  = 896;        // n_embd
constexpr int HB  = 1152;       // base hidden
constexpr int NEXP = 3;
constexpr int HEmax = 1536;

// packed bf16 weight buffer offsets (elements)
constexpr long OFS_BGU  = 0;                         // [2*HB, CD] (gate rows then up rows)
constexpr long OFS_BD   = OFS_BGU + 2L * HB * CD;    // [CD, HB]
constexpr long OFS_E0GU = OFS_BD + (long)CD * HB;
constexpr long OFS_E0D  = OFS_E0GU + 2L * 1152 * CD;
constexpr long OFS_E1GU = OFS_E0D + (long)CD * 1152;
constexpr long OFS_E1D  = OFS_E1GU + 2L * 1344 * CD;
constexpr long OFS_E2GU = OFS_E1D + (long)CD * 1344;
constexpr long OFS_E2D  = OFS_E2GU + 2L * 1536 * CD;
constexpr long WTOT     = OFS_E2D + (long)CD * 1536; // 13,934,592 elems
}

// ---- scratch (static __device__ globals: allowed; no cudaMalloc) ----
__device__ __nv_bfloat16 g_xb[(long)cfg::TOK * cfg::CD];      // x in bf16
__device__ __nv_bfloat16 g_w[cfg::WTOT];                      // all weights bf16
__device__ float         g_gu[(long)cfg::TOK * 2 * cfg::HEmax]; // gate|up GEMM out (fp32)
__device__ __nv_bfloat16 g_hb[(long)cfg::TOK * cfg::HB];      // base h (bf16)
__device__ __nv_bfloat16 g_he[(long)cfg::TOK * cfg::HEmax];   // expert h (bf16, compact)
__device__ int           g_cnt[cfg::NEXP];
__device__ int           g_idx[cfg::NEXP * cfg::TOK];
__device__ float         g_wt[cfg::TOK];

// ---- small helpers ----
__device__ __forceinline__ void cp16(void* sdst, const void* gsrc, bool pred) {
    uint32_t sa = (uint32_t)__cvta_generic_to_shared(sdst);
    int n = pred ? 16 : 0;
    asm volatile("cp.async.cg.shared.global [%0], [%1], 16, %2;\n"
                 :: "r"(sa), "l"(gsrc), "r"(n));
}
__device__ __forceinline__ void cp_commit() { asm volatile("cp.async.commit_group;\n"); }
__device__ __forceinline__ void cp_wait0()  { asm volatile("cp.async.wait_group 0;\n"); }

__device__ __forceinline__ void mma16816(float c[4], const uint32_t a[4],
                                         uint32_t b0, uint32_t b1) {
    asm volatile(
        "mma.sync.aligned.m16n8k16.row.col.f32.bf16.bf16.f32 "
        "{%0,%1,%2,%3}, {%4,%5,%6,%7}, {%8,%9}, {%0,%1,%2,%3};\n"
        : "+f"(c[0]), "+f"(c[1]), "+f"(c[2]), "+f"(c[3])
        : "r"(a[0]), "r"(a[1]), "r"(a[2]), "r"(a[3]), "r"(b0), "r"(b1));
}

// ----------------------------------------------------------------------------
// Generic GEMM: C[M,N] = A[M,K] @ B[N,K]^T  (A,B bf16 row-major, C fp32)
// BM=128 BN=128 BK=32, 256 threads (8 warps as 4x2 -> warp tile 32x64),
// cp.async 2-stage pipeline. M may be dynamic (*cntPtr). A rows optionally
// gathered through idx. Epilogues:
//   EPI 0 : Cout[m*ldc+n]            = acc
//   EPI 1 : Cout[m*ldc+n]            = Xres[m*ldc+n] + acc        (residual)
//   EPI 2 : Cout[idx[m]*ldc+n]      += wt[idx[m]] * acc           (scatter-add)
// ----------------------------------------------------------------------------
template <bool GATHER, int EPI>
__global__ __launch_bounds__(256)
void gemm_kernel(const __nv_bfloat16* __restrict__ A,
                 const __nv_bfloat16* __restrict__ Bw,
                 float* __restrict__ Cout,
                 const float* __restrict__ Xres,
                 const int* __restrict__ cntPtr,
                 const int* __restrict__ idx,
                 const float* __restrict__ wt,
                 int M, int K, int ldc)
{
    constexpr int BM = 128, BN = 128, BK = 32, PAD = 8;
    __shared__ __align__(16) __nv_bfloat16 As[2][BM][BK + PAD];
    __shared__ __align__(16) __nv_bfloat16 Bs[2][BN][BK + PAD];

    const int Mdyn = cntPtr ? *cntPtr : M;
    const int m0 = blockIdx.y * BM;
    if (m0 >= Mdyn) return;
    const int n0 = blockIdx.x * BN;

    const int tid  = threadIdx.x;
    const int lane = tid & 31;
    const int w    = tid >> 5;
    const int wm   = w >> 1;   // 0..3
    const int wn   = w & 1;    // 0..1

    const int lr = tid >> 2;        // 0..63 (load row within half-tile)
    const int lc = (tid & 3) * 8;   // 0,8,16,24 (bf16 col chunk, 16B)

    const int KT = K / BK;

    float c[2][8][4];
#pragma unroll
    for (int mi = 0; mi < 2; mi++)
#pragma unroll
        for (int nj = 0; nj < 8; nj++)
#pragma unroll
            for (int q = 0; q < 4; q++) c[mi][nj][q] = 0.f;

    auto load_stage = [&](int kt, int buf) {
        const int k0 = kt * BK;
#pragma unroll
        for (int i = 0; i < 2; i++) {
            int row = i * 64 + lr;
            int gm = m0 + row;
            bool p = gm < Mdyn;
            long srow;
            if (GATHER) srow = p ? (long)idx[gm] : 0L;
            else        srow = p ? (long)gm : 0L;
            cp16(&As[buf][row][lc], A + srow * K + k0 + lc, p);
            int gn = n0 + row;  // grid.x == N/BN, always in range
            cp16(&Bs[buf][row][lc], Bw + (long)gn * K + k0 + lc, true);
        }
        cp_commit();
    };

    load_stage(0, 0);

    for (int kt = 0; kt < KT; kt++) {
        const int buf = kt & 1;
        cp_wait0();
        __syncthreads();
        if (kt + 1 < KT) load_stage(kt + 1, buf ^ 1);

#pragma unroll
        for (int ks = 0; ks < 2; ks++) {
            const int kk = ks * 16 + (lane & 3) * 2;
            uint32_t a[2][4];
#pragma unroll
            for (int mi = 0; mi < 2; mi++) {
                int r0 = wm * 32 + mi * 16 + (lane >> 2);
                a[mi][0] = *(const uint32_t*)&As[buf][r0    ][kk];
                a[mi][1] = *(const uint32_t*)&As[buf][r0 + 8][kk];
                a[mi][2] = *(const uint32_t*)&As[buf][r0    ][kk + 8];
                a[mi][3] = *(const uint32_t*)&As[buf][r0 + 8][kk + 8];
            }
#pragma unroll
            for (int nj = 0; nj < 8; nj++) {
                int cn = wn * 64 + nj * 8 + (lane >> 2);
                uint32_t b0 = *(const uint32_t*)&Bs[buf][cn][kk];
                uint32_t b1 = *(const uint32_t*)&Bs[buf][cn][kk + 8];
                mma16816(c[0][nj], a[0], b0, b1);
                mma16816(c[1][nj], a[1], b0, b1);
            }
        }
    }

    // epilogue
#pragma unroll
    for (int mi = 0; mi < 2; mi++) {
#pragma unroll
        for (int nj = 0; nj < 8; nj++) {
            int r  = m0 + wm * 32 + mi * 16 + (lane >> 2);
            int cn = n0 + wn * 64 + nj * 8 + (lane & 3) * 2;
            const float* cp = c[mi][nj];
#pragma unroll
            for (int h = 0; h < 2; h++) {
                int rr = r + h * 8;
                if (rr < Mdyn) {
                    float v0 = cp[h * 2 + 0], v1 = cp[h * 2 + 1];
                    if (EPI == 0) {
                        *(float2*)&Cout[(long)rr * ldc + cn] = make_float2(v0, v1);
                    } else if (EPI == 1) {
                        float2 xr = *(const float2*)&Xres[(long)rr * ldc + cn];
                        *(float2*)&Cout[(long)rr * ldc + cn] =
                            make_float2(xr.x + v0, xr.y + v1);
                    } else {
                        int t = idx[rr];
                        float wv = wt[t];
                        float2* o = (float2*)&Cout[(long)t * ldc + cn];
                        float2 old = *o;
                        *o = make_float2(old.x + wv * v0, old.y + wv * v1);
                    }
                }
            }
        }
    }
}

// ---- fp32 -> bf16 convert ----
__global__ void f2bf_kernel(const float* __restrict__ s, __nv_bfloat16* __restrict__ d, long n) {
    long i = blockIdx.x * (long)blockDim.x + threadIdx.x;
    long stride = (long)gridDim.x * blockDim.x;
    for (; i < n; i += stride) d[i] = __float2bfloat16(s[i]);
}

__global__ void zero_kernel(int* cnt) {
    if (threadIdx.x < cfg::NEXP) cnt[threadIdx.x] = 0;
}

// ---- router: fp32 logits, top-1 argmax (first-index tie like jnp.argmax),
//      token compaction + per-token weight p/max(p,1e-6) ----
__global__ void router_kernel(const float* __restrict__ x, const float* __restrict__ rw,
                              const float* __restrict__ bb, int* __restrict__ cnt,
                              int* __restrict__ idxArr, float* __restrict__ wt) {
    int gw   = (blockIdx.x * blockDim.x + threadIdx.x) >> 5;
    int lane = threadIdx.x & 31;
    if (gw >= cfg::TOK) return;
    const float* xr = x + (long)gw * cfg::CD;
    float s0 = 0.f, s1 = 0.f, s2 = 0.f;
    for (int cc = lane; cc < cfg::CD; cc += 32) {
        float xv = xr[cc];
        s0 += xv * rw[cc];
        s1 += xv * rw[cfg::CD + cc];
        s2 += xv * rw[2 * cfg::CD + cc];
    }
#pragma unroll
    for (int o = 16; o > 0; o >>= 1) {
        s0 += __shfl_down_sync(0xffffffffu, s0, o);
        s1 += __shfl_down_sync(0xffffffffu, s1, o);
        s2 += __shfl_down_sync(0xffffffffu, s2, o);
    }
    if (lane == 0) {
        float l0 = s0 + bb[0], l1 = s1 + bb[1], l2 = s2 + bb[2]; // TAU == 1
        int best = 0; float lb = l0;
        if (l1 > lb) { best = 1; lb = l1; }
        if (l2 > lb) { best = 2; lb = l2; }
        float p = 1.f / (1.f + expf(-lb));
        wt[gw] = p / fmaxf(p, 1e-6f);   // == 1.0f in practice
        int pos = atomicAdd(&cnt[best], 1);
        idxArr[best * cfg::TOK + pos] = gw;
    }
}

// ---- SwiGLU activation: h[m,j] = silu(gu[m, j]) * gu[m, H + j] ----
__global__ void act_kernel(const float* __restrict__ gu, __nv_bfloat16* __restrict__ h,
                           const int* __restrict__ cntPtr, int Mstat, int H) {
    int Mdyn = cntPtr ? *cntPtr : Mstat;
    long total = (long)Mdyn * H;
    long stride = (long)gridDim.x * blockDim.x;
    for (long i = blockIdx.x * (long)blockDim.x + threadIdx.x; i < total; i += stride) {
        int m = (int)(i / H), j = (int)(i % H);
        float g = gu[(long)m * 2 * H + j];
        float u = gu[(long)m * 2 * H + H + j];
        float s = g / (1.f + __expf(-g));
        h[i] = __float2bfloat16(s * u);
    }
}

// ----------------------------------------------------------------------------
extern "C" void kernel_launch(void* const* d_in, const int* in_sizes, int n_in,
                              void* d_out, int out_size) {
    using namespace cfg;
    (void)in_sizes; (void)n_in; (void)out_size;

    const float* x   = (const float*)d_in[0];
    const float* bgw = (const float*)d_in[1];
    const float* buw = (const float*)d_in[2];
    const float* bdw = (const float*)d_in[3];
    const float* rw  = (const float*)d_in[4];
    const float* bb  = (const float*)d_in[5];
    const float* egw[3] = {(const float*)d_in[6],  (const float*)d_in[9],  (const float*)d_in[12]};
    const float* euw[3] = {(const float*)d_in[7],  (const float*)d_in[10], (const float*)d_in[13]};
    const float* edw[3] = {(const float*)d_in[8],  (const float*)d_in[11], (const float*)d_in[14]};
    float* out = (float*)d_out;

    __nv_bfloat16 *p_xb, *p_w, *p_hb, *p_he;
    float *p_gu, *p_wt;
    int *p_cnt, *p_idx;
    cudaGetSymbolAddress((void**)&p_xb,  g_xb);
    cudaGetSymbolAddress((void**)&p_w,   g_w);
    cudaGetSymbolAddress((void**)&p_gu,  g_gu);
    cudaGetSymbolAddress((void**)&p_hb,  g_hb);
    cudaGetSymbolAddress((void**)&p_he,  g_he);
    cudaGetSymbolAddress((void**)&p_cnt, g_cnt);
    cudaGetSymbolAddress((void**)&p_idx, g_idx);
    cudaGetSymbolAddress((void**)&p_wt,  g_wt);

    const int  HEs[3]    = {1152, 1344, 1536};
    const long OFS_GU[3] = {OFS_E0GU, OFS_E1GU, OFS_E2GU};
    const long OFS_D[3]  = {OFS_E0D,  OFS_E1D,  OFS_E2D};

    zero_kernel<<<1, 32>>>(p_cnt);

    // convert activations + weights to bf16
    f2bf_kernel<<<2048, 256>>>(x, p_xb, (long)TOK * CD);
    f2bf_kernel<<<512, 256>>>(bgw, p_w + OFS_BGU,                 (long)HB * CD);
    f2bf_kernel<<<512, 256>>>(buw, p_w + OFS_BGU + (long)HB * CD, (long)HB * CD);
    f2bf_kernel<<<512, 256>>>(bdw, p_w + OFS_BD,                  (long)CD * HB);
    for (int e = 0; e < 3; e++) {
        f2bf_kernel<<<512, 256>>>(egw[e], p_w + OFS_GU[e],                     (long)HEs[e] * CD);
        f2bf_kernel<<<512, 256>>>(euw[e], p_w + OFS_GU[e] + (long)HEs[e] * CD, (long)HEs[e] * CD);
        f2bf_kernel<<<512, 256>>>(edw[e], p_w + OFS_D[e],                      (long)CD * HEs[e]);
    }

    // fp32 router -> counts, compacted index lists, weights
    router_kernel<<<TOK / 8, 256>>>(x, rw, bb, p_cnt, p_idx, p_wt);

    // base gate|up:  [TOK, 2304] = xb @ Wgu^T
    gemm_kernel<false, 0><<<dim3(2 * HB / 128, TOK / 128), 256>>>(
        p_xb, p_w + OFS_BGU, p_gu, nullptr, nullptr, nullptr, nullptr, TOK, CD, 2 * HB);
    act_kernel<<<2048, 256>>>(p_gu, p_hb, nullptr, TOK, HB);
    // base down with residual: out = x + hb @ Wd^T
    gemm_kernel<false, 1><<<dim3(CD / 128, TOK / 128), 256>>>(
        p_hb, p_w + OFS_BD, out, x, nullptr, nullptr, nullptr, TOK, HB, CD);

    // experts (gathered rows; dynamic M = cnt[e]; down scatter-adds into out)
    for (int e = 0; e < 3; e++) {
        int H = HEs[e];
        gemm_kernel<true, 0><<<dim3(2 * H / 128, TOK / 128), 256>>>(
            p_xb, p_w + OFS_GU[e], p_gu, nullptr, p_cnt + e, p_idx + e * TOK, nullptr,
            TOK, CD, 2 * H);
        act_kernel<<<2048, 256>>>(p_gu, p_he, p_cnt + e, TOK, H);
        gemm_kernel<false, 2><<<dim3(CD / 128, TOK / 128), 256>>>(
            p_he, p_w + OFS_D[e], out, nullptr, p_cnt + e, p_idx + e * TOK, p_wt,
            TOK, H, CD);
    }
}